// round 1
// baseline (speedup 1.0000x reference)
#include <cuda_runtime.h>

#define B_ 2
#define T_ 192
#define NH 8
#define DH 64
#define DM 512

// ---------------- device scratch (static, no allocs) ----------------
__device__ float g_proj[5*B_*NH*T_*DH];      // a,b,c,d,e  [sel][b][n][t][h]
__device__ float g_bsum[B_*T_*DH];           // sum over heads of b-proj
__device__ float g_wkT[NH*DH*4096];          // W_K transposed: [n][k][i*64+j]
__device__ float g_step1[B_*T_*4096];        // [b][r][i*64+j]
__device__ float g_step2[(size_t)B_*T_*DH*T_]; // [b][r][i][q]
__device__ float g_dv[(size_t)B_*NH*T_*DH*DH]; // [b][n][p][g][k]
__device__ float g_z[B_*T_*NH*DH];           // [b][r][n][k]

__device__ __forceinline__ int proj_off(int sel,int b,int n,int t,int h){
  return (((sel*B_+b)*NH+n)*T_+t)*DH+h;
}

// ---------------- projections a..e ----------------
__global__ __launch_bounds__(256) void k_proj(
  const float* __restrict__ x,
  const float* __restrict__ wA, const float* __restrict__ wB,
  const float* __restrict__ wC, const float* __restrict__ wD,
  const float* __restrict__ wE,
  const float* __restrict__ bA, const float* __restrict__ bB,
  const float* __restrict__ bC, const float* __restrict__ bD,
  const float* __restrict__ bE)
{
  int sel = blockIdx.y >> 3, n = blockIdx.y & 7;
  int tok0 = blockIdx.x * 8;
  int b = tok0 / T_, t0 = tok0 % T_;
  const float* W; const float* bias;
  switch(sel){
    case 0: W=wA; bias=bA; break;
    case 1: W=wB; bias=bB; break;
    case 2: W=wC; bias=bC; break;
    case 3: W=wD; bias=bD; break;
    default: W=wE; bias=bE; break;
  }
  W += n*DM*DH; bias += n*DH;
  __shared__ float xs[8][DM];
  __shared__ float wsm[64][DH];
  int tid = threadIdx.x;
  for (int idx=tid; idx<8*DM; idx+=256)
    xs[idx>>9][idx&511] = x[(tok0 + (idx>>9))*DM + (idx&511)];
  int h = tid & 63, tg = tid >> 6;
  float acc0=0.f, acc1=0.f;
  for (int dd0=0; dd0<DM; dd0+=64){
    __syncthreads();
    for (int idx=tid; idx<64*DH; idx+=256)
      wsm[idx>>6][idx&63] = W[(dd0+(idx>>6))*DH + (idx&63)];
    __syncthreads();
    #pragma unroll 16
    for (int dd=0; dd<64; dd++){
      float wv = wsm[dd][h];
      acc0 += xs[2*tg  ][dd0+dd]*wv;
      acc1 += xs[2*tg+1][dd0+dd]*wv;
    }
  }
  float bv = bias[h];
  g_proj[proj_off(sel,b,n,t0+2*tg  ,h)] = acc0+bv;
  g_proj[proj_off(sel,b,n,t0+2*tg+1,h)] = acc1+bv;
}

// ---------------- bsum over heads ----------------
__global__ void k_bsum(){
  int idx = blockIdx.x*256 + threadIdx.x;
  if (idx >= B_*T_*DH) return;
  int b = idx / (T_*DH); int qj = idx % (T_*DH);
  float s = 0.f;
  #pragma unroll
  for (int n=0;n<NH;n++) s += g_proj[((1*B_+b)*NH+n)*T_*DH + qj];
  g_bsum[idx] = s;
}

// ---------------- W_K transpose to [n][k][ij] ----------------
__global__ void k_wkT(const float* __restrict__ WK){
  int o = blockIdx.x*256 + threadIdx.x;
  if (o >= NH*DH*4096) return;
  int n = o >> 18; int rem = o & 262143;
  int k = rem >> 12; int ij = rem & 4095;
  int i = ij >> 6, j = ij & 63;
  g_wkT[o] = WK[((n*64+i)*64+j)*64 + k];
}

// ---------------- step1[b,r,i,j] = sum_{n,k} c * W_K ----------------
__global__ __launch_bounds__(256) void k_step1(){
  int tok0 = blockIdx.x*8; int b = tok0/T_, t0 = tok0%T_;
  int colbase = blockIdx.y*512;
  __shared__ float cs[8][512];
  int tid = threadIdx.x;
  for (int idx=tid; idx<4096; idx+=256){
    int t = idx>>9, nk = idx&511, n = nk>>6, k = nk&63;
    cs[t][nk] = g_proj[proj_off(2,b,n,t0+t,k)];
  }
  __syncthreads();
  float acc[8][2];
  #pragma unroll
  for (int t=0;t<8;t++){acc[t][0]=0.f;acc[t][1]=0.f;}
  const float* wbase = g_wkT + colbase + tid;
  for (int nk=0; nk<512; nk++){
    float w0 = wbase[nk*4096];
    float w1 = wbase[nk*4096+256];
    #pragma unroll
    for (int t=0;t<8;t++){
      float cv = cs[t][nk];
      acc[t][0] += cv*w0; acc[t][1] += cv*w1;
    }
  }
  for (int t=0;t<8;t++){
    g_step1[(b*T_+t0+t)*4096 + colbase + tid      ] = acc[t][0];
    g_step1[(b*T_+t0+t)*4096 + colbase + tid + 256] = acc[t][1];
  }
}

// ---------------- step2[b,r,i,q] = sum_j step1 * bsum ----------------
__global__ __launch_bounds__(256) void k_step2(){
  int rowtile = blockIdx.x;           // 0..383
  int r = rowtile >> 1, i0 = (rowtile & 1)*32;
  int b = blockIdx.y;
  extern __shared__ float s2sm[];
  float* s1s = s2sm;                  // [32][64]
  float* bsm = s2sm + 2048;           // [192][65] padded
  int tid = threadIdx.x;
  const float* s1src = g_step1 + (b*T_+r)*4096 + i0*64;
  for (int idx=tid; idx<2048; idx+=256) s1s[idx] = s1src[idx];
  for (int idx=tid; idx<T_*64; idx+=256){
    int q = idx>>6, j = idx&63;
    bsm[q*65+j] = g_bsum[b*T_*64 + idx];
  }
  __syncthreads();
  int q0 = tid & 31, ir = tid >> 5;
  float acc[4][6];
  #pragma unroll
  for (int a1=0;a1<4;a1++){ 
    #pragma unroll
    for(int m=0;m<6;m++) acc[a1][m]=0.f; }
  for (int j=0;j<64;j++){
    float s1v[4];
    #pragma unroll
    for (int rr=0;rr<4;rr++) s1v[rr] = s1s[(ir*4+rr)*64 + j];
    float bv[6];
    #pragma unroll
    for (int m=0;m<6;m++) bv[m] = bsm[(q0+32*m)*65 + j];
    #pragma unroll
    for (int rr=0;rr<4;rr++)
      #pragma unroll
      for (int m=0;m<6;m++)
        acc[rr][m] += s1v[rr]*bv[m];
  }
  for (int rr=0;rr<4;rr++){
    int iloc = i0 + ir*4 + rr;
    float* dst = g_step2 + ((size_t)(b*T_+r)*64 + iloc)*T_;
    #pragma unroll
    for (int m=0;m<6;m++) dst[q0+32*m] = acc[rr][m];
  }
}

// ---------------- dv[b,n,p,g,k] = sum_h d * W_V ----------------
__global__ __launch_bounds__(256) void k_dv(const float* __restrict__ WV){
  int p0 = blockIdx.x*4;
  int gh = blockIdx.y;
  int bn = blockIdx.z; int b = bn>>3, n = bn&7;
  __shared__ float ds[4][64];
  int tid = threadIdx.x;
  ds[tid>>6][tid&63] = g_proj[proj_off(3,b,n,p0+(tid>>6),tid&63)];
  __syncthreads();
  int k = tid & 63, g0 = gh*32 + (tid>>6);
  float acc[4][8];
  #pragma unroll
  for(int p=0;p<4;p++){
    #pragma unroll
    for(int g=0;g<8;g++) acc[p][g]=0.f; }
  for (int h=0;h<64;h++){
    float d0=ds[0][h], d1=ds[1][h], d2=ds[2][h], d3=ds[3][h];
    const float* wp = WV + ((n*64+h)*64 + g0)*64 + k;
    #pragma unroll
    for (int gg=0;gg<8;gg++){
      float wv = wp[gg*256];
      acc[0][gg]+=d0*wv; acc[1][gg]+=d1*wv; acc[2][gg]+=d2*wv; acc[3][gg]+=d3*wv;
    }
  }
  for (int pp=0;pp<4;pp++)
    #pragma unroll
    for (int gg=0;gg<8;gg++){
      int g = g0 + 4*gg;
      g_dv[(((size_t)(b*NH+n)*T_ + p0+pp)*64 + g)*64 + k] = acc[pp][gg];
    }
}

// ---------------- main fused scores/softmax/z kernel ----------------
// one CTA per (b, n, r). max-free softmax (scores are tiny; masked entries
// underflow exp to exactly 0, matching the reference bit-wise in fp32).
__global__ __launch_bounds__(256) void k_main(){
  int r = blockIdx.x, n = blockIdx.y, b = blockIdx.z;
  int tid = threadIdx.x;
  float* zout = g_z + ((b*T_+r)*NH + n)*DH;
  if (r == 0){ if (tid < 64) zout[tid] = 0.f; return; }
  extern __shared__ float sm[];
  float* s2s = sm;             // 12288 : step2[r][i][q]
  float* as_ = sm + 12288;     // 12288 : a[p][i]
  float* es_ = sm + 24576;     // 12288 : e[q][g]
  float* ps_ = sm + 36864;     // 1024  : per-warp P transpose (float4 x32)
  float* wsm = sm + 37888;     // 2048  : per-warp w[4][64]
  float* zpt = sm + 39936;     // 512
  float* lpt = sm + 40448;     // 8
  const float* s2src = g_step2 + (size_t)(b*T_+r)*64*T_;
  for (int idx=tid; idx<12288; idx+=256) s2s[idx] = s2src[idx];
  const float* asrc = g_proj + proj_off(0,b,n,0,0);
  for (int idx=tid; idx<12288; idx+=256) as_[idx] = asrc[idx];
  const float* esrc = g_proj + proj_off(4,b,n,0,0);
  for (int idx=tid; idx<12288; idx+=256) es_[idx] = esrc[idx];
  __syncthreads();
  int warp = tid >> 5, lane = tid & 31;
  float4* psw = (float4*)(ps_ + warp*128);
  float* wsw = wsm + warp*256;
  float2 zloc = make_float2(0.f,0.f);
  float lacc = 0.f;
  int ntiles = (r+3)>>2;
  const float* dvbn = g_dv + (size_t)(b*NH+n)*T_*4096;
  for (int t = warp; t < ntiles; t += 8){
    int p0 = t*4;
    float w00=0,w01=0,w10=0,w11=0,w20=0,w21=0,w30=0,w31=0;
    for (int qc=0; qc<6; qc++){
      int q = qc*32 + lane;
      float a0=0,a1=0,a2=0,a3=0;
      const float* ap  = as_ + p0*64;
      const float* s2q = s2s + q;
      #pragma unroll
      for (int i=0;i<64;i+=4){
        float4 A0 = *(const float4*)(ap + i);
        float4 A1 = *(const float4*)(ap + 64 + i);
        float4 A2 = *(const float4*)(ap + 128 + i);
        float4 A3 = *(const float4*)(ap + 192 + i);
        float s0 = s2q[(i  )*192];
        float s1 = s2q[(i+1)*192];
        float s2v= s2q[(i+2)*192];
        float s3 = s2q[(i+3)*192];
        a0 += A0.x*s0; a0 += A0.y*s1; a0 += A0.z*s2v; a0 += A0.w*s3;
        a1 += A1.x*s0; a1 += A1.y*s1; a1 += A1.z*s2v; a1 += A1.w*s3;
        a2 += A2.x*s0; a2 += A2.y*s1; a2 += A2.z*s2v; a2 += A2.w*s3;
        a3 += A3.x*s0; a3 += A3.y*s1; a3 += A3.z*s2v; a3 += A3.w*s3;
      }
      const float sc = 1.0f/64.0f;
      float P0=0.f,P1=0.f,P2=0.f,P3=0.f;
      if (p0+0 < r && q > p0+0) P0 = __expf(a0*sc);
      if (p0+1 < r && q > p0+1) P1 = __expf(a1*sc);
      if (p0+2 < r && q > p0+2) P2 = __expf(a2*sc);
      if (p0+3 < r && q > p0+3) P3 = __expf(a3*sc);
      lacc += P0+P1+P2+P3;
      psw[lane] = make_float4(P0,P1,P2,P3);
      __syncwarp();
      const float* eb = es_ + (qc*32)*64;
      #pragma unroll 8
      for (int qq=0; qq<32; qq++){
        float4 Pq = psw[qq];
        float e0 = eb[qq*64 + lane];
        float e1 = eb[qq*64 + lane + 32];
        w00 += Pq.x*e0; w01 += Pq.x*e1;
        w10 += Pq.y*e0; w11 += Pq.y*e1;
        w20 += Pq.z*e0; w21 += Pq.z*e1;
        w30 += Pq.w*e0; w31 += Pq.w*e1;
      }
      __syncwarp();
    }
    wsw[0*64+lane] = w00; wsw[0*64+lane+32] = w01;
    wsw[1*64+lane] = w10; wsw[1*64+lane+32] = w11;
    wsw[2*64+lane] = w20; wsw[2*64+lane+32] = w21;
    wsw[3*64+lane] = w30; wsw[3*64+lane+32] = w31;
    __syncwarp();
    int pmax = min(4, r - p0);
    for (int pp=0; pp<pmax; pp++){
      const float* dvp = dvbn + (size_t)(p0+pp)*4096 + 2*lane;
      const float* wrow = wsw + pp*64;
      #pragma unroll 8
      for (int g=0; g<64; g++){
        float wv = wrow[g];
        float2 d2 = *(const float2*)(dvp + g*64);
        zloc.x += wv*d2.x;
        zloc.y += wv*d2.y;
      }
    }
    __syncwarp();
  }
  zpt[warp*64 + 2*lane  ] = zloc.x;
  zpt[warp*64 + 2*lane+1] = zloc.y;
  #pragma unroll
  for (int off=16; off>0; off>>=1)
    lacc += __shfl_xor_sync(0xffffffffu, lacc, off);
  if (lane==0) lpt[warp] = lacc;
  __syncthreads();
  if (tid < 64){
    float zs = 0.f, lt = 0.f;
    #pragma unroll
    for (int w=0; w<8; w++){ zs += zpt[w*64+tid]; lt += lpt[w]; }
    zout[tid] = zs / lt;
  }
}

// ---------------- output projection ----------------
__global__ __launch_bounds__(256) void k_out(const float* __restrict__ WO,
                                             const float* __restrict__ bO,
                                             float* __restrict__ out){
  int tok0 = blockIdx.x*4;
  __shared__ float zs[4][512];
  int tid = threadIdx.x;
  for (int idx=tid; idx<4*512; idx+=256)
    zs[idx>>9][idx&511] = g_z[(tok0+(idx>>9))*512 + (idx&511)];
  __syncthreads();
  float acc[4][2];
  #pragma unroll
  for(int t=0;t<4;t++){acc[t][0]=0.f;acc[t][1]=0.f;}
  for (int nh=0; nh<512; nh++){
    float w0 = WO[nh*512 + tid      ];
    float w1 = WO[nh*512 + tid + 256];
    #pragma unroll
    for (int t=0;t<4;t++){
      float zv = zs[t][nh];
      acc[t][0] += zv*w0; acc[t][1] += zv*w1;
    }
  }
  float b0 = bO[tid], b1 = bO[tid+256];
  for (int t=0;t<4;t++){
    out[(tok0+t)*512 + tid      ] = acc[t][0] + b0;
    out[(tok0+t)*512 + tid + 256] = acc[t][1] + b1;
  }
}

// ---------------- launch ----------------
extern "C" void kernel_launch(void* const* d_in, const int* in_sizes, int n_in,
                              void* d_out, int out_size){
  const float* x  = (const float*)d_in[0];
  const float* wA = (const float*)d_in[1];
  const float* wB = (const float*)d_in[2];
  const float* wC = (const float*)d_in[3];
  const float* wD = (const float*)d_in[4];
  const float* wE = (const float*)d_in[5];
  const float* WK = (const float*)d_in[6];
  const float* WV = (const float*)d_in[7];
  const float* WO = (const float*)d_in[8];
  const float* bA = (const float*)d_in[9];
  const float* bB = (const float*)d_in[10];
  const float* bC = (const float*)d_in[11];
  const float* bD = (const float*)d_in[12];
  const float* bE = (const float*)d_in[13];
  const float* bO = (const float*)d_in[14];
  float* out = (float*)d_out;

  k_proj<<<dim3(48,40),256>>>(x,wA,wB,wC,wD,wE,bA,bB,bC,bD,bE);
  k_bsum<<<(B_*T_*DH+255)/256,256>>>();
  k_wkT<<<(NH*DH*4096+255)/256,256>>>(WK);
  k_step1<<<dim3(48,8),256>>>();
  size_t s2smem = (2048 + 192*65)*sizeof(float);
  cudaFuncSetAttribute(k_step2, cudaFuncAttributeMaxDynamicSharedMemorySize, (int)s2smem);
  k_step2<<<dim3(384,2),256,s2smem>>>();
  k_dv<<<dim3(48,2,16),256>>>(WV);
  size_t msmem = 40456*sizeof(float);
  cudaFuncSetAttribute(k_main, cudaFuncAttributeMaxDynamicSharedMemorySize, (int)msmem);
  k_main<<<dim3(T_,NH,B_),256,msmem>>>();
  k_out<<<96,256>>>(WO,bO,out);
}

// round 3
// speedup vs baseline: 1.7063x; 1.7063x over previous
#include <cuda_runtime.h>

#define B_ 2
#define T_ 192
#define NH 8
#define DH 64
#define DM 512

// ---------------- device scratch (static, no allocs) ----------------
__device__ float g_proj[5*B_*NH*T_*DH];      // a,b,c,d,e  [sel][b][n][t][h]
__device__ float g_bsum[B_*T_*DH];           // sum over heads of b-proj
__device__ float g_wkT[NH*DH*4096];          // W_K transposed: [n][k][i*64+j]
__device__ float g_step1[B_*T_*4096];        // [b][r][i*64+j]
__device__ float g_step2[(size_t)B_*T_*DH*T_]; // [b][r][i][q]
__device__ float g_dv[(size_t)B_*NH*T_*DH*DH]; // [b][n][p][g][k]
__device__ float g_z[B_*T_*NH*DH];           // [b][r][n][k]

__device__ __forceinline__ int proj_off(int sel,int b,int n,int t,int h){
  return (((sel*B_+b)*NH+n)*T_+t)*DH+h;
}

// ---------------- projections a..e ----------------
__global__ __launch_bounds__(256) void k_proj(
  const float* __restrict__ x,
  const float* __restrict__ wA, const float* __restrict__ wB,
  const float* __restrict__ wC, const float* __restrict__ wD,
  const float* __restrict__ wE,
  const float* __restrict__ bA, const float* __restrict__ bB,
  const float* __restrict__ bC, const float* __restrict__ bD,
  const float* __restrict__ bE)
{
  int sel = blockIdx.y >> 3, n = blockIdx.y & 7;
  int tok0 = blockIdx.x * 8;
  int b = tok0 / T_, t0 = tok0 % T_;
  const float* W; const float* bias;
  switch(sel){
    case 0: W=wA; bias=bA; break;
    case 1: W=wB; bias=bB; break;
    case 2: W=wC; bias=bC; break;
    case 3: W=wD; bias=bD; break;
    default: W=wE; bias=bE; break;
  }
  W += n*DM*DH; bias += n*DH;
  __shared__ float xs[8][DM];
  __shared__ float wsm[64][DH];
  int tid = threadIdx.x;
  for (int idx=tid; idx<8*DM; idx+=256)
    xs[idx>>9][idx&511] = x[(tok0 + (idx>>9))*DM + (idx&511)];
  int h = tid & 63, tg = tid >> 6;
  float acc0=0.f, acc1=0.f;
  for (int dd0=0; dd0<DM; dd0+=64){
    __syncthreads();
    for (int idx=tid; idx<64*DH; idx+=256)
      wsm[idx>>6][idx&63] = W[(dd0+(idx>>6))*DH + (idx&63)];
    __syncthreads();
    #pragma unroll 16
    for (int dd=0; dd<64; dd++){
      float wv = wsm[dd][h];
      acc0 += xs[2*tg  ][dd0+dd]*wv;
      acc1 += xs[2*tg+1][dd0+dd]*wv;
    }
  }
  float bv = bias[h];
  g_proj[proj_off(sel,b,n,t0+2*tg  ,h)] = acc0+bv;
  g_proj[proj_off(sel,b,n,t0+2*tg+1,h)] = acc1+bv;
}

// ---------------- bsum over heads ----------------
__global__ void k_bsum(){
  int idx = blockIdx.x*256 + threadIdx.x;
  if (idx >= B_*T_*DH) return;
  int b = idx / (T_*DH); int qj = idx % (T_*DH);
  float s = 0.f;
  #pragma unroll
  for (int n=0;n<NH;n++) s += g_proj[((1*B_+b)*NH+n)*T_*DH + qj];
  g_bsum[idx] = s;
}

// ---------------- W_K transpose to [n][k][ij] ----------------
__global__ void k_wkT(const float* __restrict__ WK){
  int o = blockIdx.x*256 + threadIdx.x;
  if (o >= NH*DH*4096) return;
  int n = o >> 18; int rem = o & 262143;
  int k = rem >> 12; int ij = rem & 4095;
  int i = ij >> 6, j = ij & 63;
  g_wkT[o] = WK[((n*64+i)*64+j)*64 + k];
}

// ---------------- step1: C[384,4096] = c[384,512] x wkT[512,4096] ----------------
// CTA tile: 16 tok x 256 col, 4x4 register blocking, smem-staged operands.
__global__ __launch_bounds__(256) void k_step1(){
  int tok0 = blockIdx.x*16; int b = tok0/T_, t0 = tok0%T_;
  int col0 = blockIdx.y*256;
  extern __shared__ float s1sm[];
  float* cT = s1sm;           // [512 nk][16 t]  = 8192 floats (32KB)
  float* ws = s1sm + 8192;    // [64 nk][256 col] = 16384 floats (64KB)
  int tid = threadIdx.x;
  for (int idx=tid; idx<512*16; idx+=256){
    int t = idx>>9, nk = idx&511;
    int nn = nk>>6, k = nk&63;
    cT[nk*16 + t] = g_proj[proj_off(2,b,nn,t0+t,k)];
  }
  int colq = tid & 63, tg = tid >> 6;
  float acc[4][4];
  #pragma unroll
  for (int i=0;i<4;i++){
    #pragma unroll
    for (int j=0;j<4;j++) acc[i][j]=0.f;
  }
  for (int nkc=0; nkc<8; nkc++){
    __syncthreads();
    const float* wsrc = g_wkT + (size_t)nkc*64*4096 + col0;
    for (int idx=tid; idx<64*256; idx+=256)
      ws[idx] = wsrc[(idx>>8)*4096 + (idx&255)];
    __syncthreads();
    #pragma unroll 8
    for (int nk=0; nk<64; nk++){
      float4 cv = *(const float4*)&cT[(nkc*64+nk)*16 + 4*tg];
      float4 wv = *(const float4*)&ws[nk*256 + 4*colq];
      acc[0][0]+=cv.x*wv.x; acc[0][1]+=cv.x*wv.y; acc[0][2]+=cv.x*wv.z; acc[0][3]+=cv.x*wv.w;
      acc[1][0]+=cv.y*wv.x; acc[1][1]+=cv.y*wv.y; acc[1][2]+=cv.y*wv.z; acc[1][3]+=cv.y*wv.w;
      acc[2][0]+=cv.z*wv.x; acc[2][1]+=cv.z*wv.y; acc[2][2]+=cv.z*wv.z; acc[2][3]+=cv.z*wv.w;
      acc[3][0]+=cv.w*wv.x; acc[3][1]+=cv.w*wv.y; acc[3][2]+=cv.w*wv.z; acc[3][3]+=cv.w*wv.w;
    }
  }
  #pragma unroll
  for (int i=0;i<4;i++){
    float* dst = g_step1 + (size_t)(b*T_+t0+4*tg+i)*4096 + col0 + 4*colq;
    *(float4*)dst = make_float4(acc[i][0],acc[i][1],acc[i][2],acc[i][3]);
  }
}

// ---------------- step2[b,r,i,q] = sum_j step1 * bsum ----------------
__global__ __launch_bounds__(256) void k_step2(){
  int rowtile = blockIdx.x;           // 0..383
  int r = rowtile >> 1, i0 = (rowtile & 1)*32;
  int b = blockIdx.y;
  extern __shared__ float s2sm[];
  float* s1s = s2sm;                  // [32][64]
  float* bsm = s2sm + 2048;           // [192][65] padded
  int tid = threadIdx.x;
  const float* s1src = g_step1 + (b*T_+r)*4096 + i0*64;
  for (int idx=tid; idx<2048; idx+=256) s1s[idx] = s1src[idx];
  for (int idx=tid; idx<T_*64; idx+=256){
    int q = idx>>6, j = idx&63;
    bsm[q*65+j] = g_bsum[b*T_*64 + idx];
  }
  __syncthreads();
  int q0 = tid & 31, ir = tid >> 5;
  float acc[4][6];
  #pragma unroll
  for (int a1=0;a1<4;a1++){
    #pragma unroll
    for(int m=0;m<6;m++) acc[a1][m]=0.f; }
  for (int j=0;j<64;j++){
    float s1v[4];
    #pragma unroll
    for (int rr=0;rr<4;rr++) s1v[rr] = s1s[(ir*4+rr)*64 + j];
    float bv[6];
    #pragma unroll
    for (int m=0;m<6;m++) bv[m] = bsm[(q0+32*m)*65 + j];
    #pragma unroll
    for (int rr=0;rr<4;rr++)
      #pragma unroll
      for (int m=0;m<6;m++)
        acc[rr][m] += s1v[rr]*bv[m];
  }
  for (int rr=0;rr<4;rr++){
    int iloc = i0 + ir*4 + rr;
    float* dst = g_step2 + ((size_t)(b*T_+r)*64 + iloc)*T_;
    #pragma unroll
    for (int m=0;m<6;m++) dst[q0+32*m] = acc[rr][m];
  }
}

// ---------------- dv[b,n,p,g,k] = sum_h d * W_V ----------------
__global__ __launch_bounds__(256) void k_dv(const float* __restrict__ WV){
  int p0 = blockIdx.x*4;
  int gh = blockIdx.y;
  int bn = blockIdx.z; int b = bn>>3, n = bn&7;
  __shared__ float ds[4][64];
  int tid = threadIdx.x;
  ds[tid>>6][tid&63] = g_proj[proj_off(3,b,n,p0+(tid>>6),tid&63)];
  __syncthreads();
  int k = tid & 63, g0 = gh*32 + (tid>>6);
  float acc[4][8];
  #pragma unroll
  for(int p=0;p<4;p++){
    #pragma unroll
    for(int g=0;g<8;g++) acc[p][g]=0.f; }
  for (int h=0;h<64;h++){
    float d0=ds[0][h], d1=ds[1][h], d2=ds[2][h], d3=ds[3][h];
    const float* wp = WV + ((n*64+h)*64 + g0)*64 + k;
    #pragma unroll
    for (int gg=0;gg<8;gg++){
      float wv = wp[gg*256];
      acc[0][gg]+=d0*wv; acc[1][gg]+=d1*wv; acc[2][gg]+=d2*wv; acc[3][gg]+=d3*wv;
    }
  }
  for (int pp=0;pp<4;pp++)
    #pragma unroll
    for (int gg=0;gg<8;gg++){
      int g = g0 + 4*gg;
      g_dv[(((size_t)(b*NH+n)*T_ + p0+pp)*64 + g)*64 + k] = acc[pp][gg];
    }
}

// ---------------- main fused scores/softmax/z kernel ----------------
// one CTA per (b, n, r-pair). max-free softmax; masked q-chunks skipped;
// dv read once per p-row serves both r values.
__global__ __launch_bounds__(384) void k_main(){
  int rp = 95 - blockIdx.x;           // heavy CTAs first
  int r0 = rp*2, r1 = r0+1;
  int n = blockIdx.y, b = blockIdx.z;
  int tid = threadIdx.x;
  extern __shared__ float sm[];
  float* s20 = sm;                    // 12288 : step2[r0][i][q]
  float* s21 = sm + 12288;            // 12288 : step2[r1][i][q]
  float* as_ = sm + 24576;            // 12288 : a[p][i]
  float* es_ = sm + 36864;            // 12288 : e[q][g]
  float* pwb = sm + 49152;            // 12 warps x 512 (P bufs / w rows, reused)
  float* zpt = sm + 55296;            // 12 x 128
  float* lpt = sm + 56832;            // 24
  const float* s2src0 = g_step2 + (size_t)(b*T_+r0)*64*T_;
  const float* s2src1 = g_step2 + (size_t)(b*T_+r1)*64*T_;
  for (int idx=tid; idx<12288; idx+=384){ s20[idx]=s2src0[idx]; s21[idx]=s2src1[idx]; }
  const float* asrc = g_proj + proj_off(0,b,n,0,0);
  const float* esrc = g_proj + proj_off(4,b,n,0,0);
  for (int idx=tid; idx<12288; idx+=384){ as_[idx]=asrc[idx]; es_[idx]=esrc[idx]; }
  __syncthreads();
  int warp = tid >> 5, lane = tid & 31;
  float* pw = pwb + warp*512;
  float4* psw0 = (float4*)pw;         // 32 float4 (P for r0)
  float4* psw1 = (float4*)(pw + 128); // 32 float4 (P for r1)
  float z0x=0.f,z0y=0.f,z1x=0.f,z1y=0.f,l0=0.f,l1=0.f;
  int ntiles = (r1+3)>>2;
  const float* dvbn = g_dv + (size_t)(b*NH+n)*T_*4096;
  const float sc = 0.015625f;
  for (int t = warp; t < ntiles; t += 12){
    int p0 = t*4;
    float w0[8], w1[8];
    #pragma unroll
    for (int j=0;j<8;j++){ w0[j]=0.f; w1[j]=0.f; }
    for (int qc = p0>>5; qc < 6; qc++){
      int q = qc*32 + lane;
      float a00=0.f,a01=0.f,a02=0.f,a03=0.f;
      float a10=0.f,a11=0.f,a12=0.f,a13=0.f;
      const float* ap  = as_ + p0*64;
      const float* q0p = s20 + q;
      const float* q1p = s21 + q;
      #pragma unroll
      for (int i=0;i<64;i+=4){
        float4 A0 = *(const float4*)(ap + i);
        float4 A1 = *(const float4*)(ap + 64 + i);
        float4 A2 = *(const float4*)(ap + 128 + i);
        float4 A3 = *(const float4*)(ap + 192 + i);
        float s0a=q0p[(i)*192], s0b=q0p[(i+1)*192], s0c=q0p[(i+2)*192], s0d=q0p[(i+3)*192];
        float s1a=q1p[(i)*192], s1b=q1p[(i+1)*192], s1c=q1p[(i+2)*192], s1d=q1p[(i+3)*192];
        a00+=A0.x*s0a; a00+=A0.y*s0b; a00+=A0.z*s0c; a00+=A0.w*s0d;
        a01+=A1.x*s0a; a01+=A1.y*s0b; a01+=A1.z*s0c; a01+=A1.w*s0d;
        a02+=A2.x*s0a; a02+=A2.y*s0b; a02+=A2.z*s0c; a02+=A2.w*s0d;
        a03+=A3.x*s0a; a03+=A3.y*s0b; a03+=A3.z*s0c; a03+=A3.w*s0d;
        a10+=A0.x*s1a; a10+=A0.y*s1b; a10+=A0.z*s1c; a10+=A0.w*s1d;
        a11+=A1.x*s1a; a11+=A1.y*s1b; a11+=A1.z*s1c; a11+=A1.w*s1d;
        a12+=A2.x*s1a; a12+=A2.y*s1b; a12+=A2.z*s1c; a12+=A2.w*s1d;
        a13+=A3.x*s1a; a13+=A3.y*s1b; a13+=A3.z*s1c; a13+=A3.w*s1d;
      }
      float P00 = (p0+0<r0 && q>p0+0) ? __expf(a00*sc) : 0.f;
      float P01 = (p0+1<r0 && q>p0+1) ? __expf(a01*sc) : 0.f;
      float P02 = (p0+2<r0 && q>p0+2) ? __expf(a02*sc) : 0.f;
      float P03 = (p0+3<r0 && q>p0+3) ? __expf(a03*sc) : 0.f;
      float P10 = (p0+0<r1 && q>p0+0) ? __expf(a10*sc) : 0.f;
      float P11 = (p0+1<r1 && q>p0+1) ? __expf(a11*sc) : 0.f;
      float P12 = (p0+2<r1 && q>p0+2) ? __expf(a12*sc) : 0.f;
      float P13 = (p0+3<r1 && q>p0+3) ? __expf(a13*sc) : 0.f;
      l0 += P00+P01+P02+P03;
      l1 += P10+P11+P12+P13;
      psw0[lane] = make_float4(P00,P01,P02,P03);
      psw1[lane] = make_float4(P10,P11,P12,P13);
      __syncwarp();
      const float* eb = es_ + qc*2048;
      #pragma unroll 8
      for (int qq=0; qq<32; qq++){
        float e0 = eb[qq*64 + lane];
        float e1 = eb[qq*64 + lane + 32];
        float4 Pa = psw0[qq];
        float4 Pb = psw1[qq];
        w0[0]+=Pa.x*e0; w0[1]+=Pa.x*e1;
        w0[2]+=Pa.y*e0; w0[3]+=Pa.y*e1;
        w0[4]+=Pa.z*e0; w0[5]+=Pa.z*e1;
        w0[6]+=Pa.w*e0; w0[7]+=Pa.w*e1;
        w1[0]+=Pb.x*e0; w1[1]+=Pb.x*e1;
        w1[2]+=Pb.y*e0; w1[3]+=Pb.y*e1;
        w1[4]+=Pb.z*e0; w1[5]+=Pb.z*e1;
        w1[6]+=Pb.w*e0; w1[7]+=Pb.w*e1;
      }
      __syncwarp();
    }
    // dump w rows to per-warp smem (reuses P buffers; warp-private)
    __syncwarp();
    #pragma unroll
    for (int pp=0;pp<4;pp++){
      pw[pp*128 + lane     ] = w0[2*pp];
      pw[pp*128 + lane + 32] = w0[2*pp+1];
      pw[pp*128 + lane + 64] = w1[2*pp];
      pw[pp*128 + lane + 96] = w1[2*pp+1];
    }
    __syncwarp();
    int pmax = min(4, r1 - p0);
    for (int pp=0; pp<pmax; pp++){
      const float* dvp = dvbn + (size_t)(p0+pp)*4096 + 2*lane;
      const float* w0r = pw + pp*128;
      const float* w1r = w0r + 64;
      #pragma unroll 8
      for (int g=0; g<64; g++){
        float2 d2 = *(const float2*)(dvp + g*64);
        float wv0 = w0r[g], wv1 = w1r[g];
        z0x += wv0*d2.x; z0y += wv0*d2.y;
        z1x += wv1*d2.x; z1y += wv1*d2.y;
      }
    }
    __syncwarp();
  }
  zpt[warp*128 + 2*lane    ] = z0x;
  zpt[warp*128 + 2*lane + 1] = z0y;
  zpt[warp*128 + 2*lane + 64] = z1x;
  zpt[warp*128 + 2*lane + 65] = z1y;
  #pragma unroll
  for (int off=16; off>0; off>>=1){
    l0 += __shfl_xor_sync(0xffffffffu, l0, off);
    l1 += __shfl_xor_sync(0xffffffffu, l1, off);
  }
  if (lane==0){ lpt[warp*2]=l0; lpt[warp*2+1]=l1; }
  __syncthreads();
  if (tid < 128){
    int rr = tid >> 6, k = tid & 63;
    float zs=0.f, lt=0.f;
    #pragma unroll
    for (int w=0; w<12; w++){ zs += zpt[w*128 + rr*64 + k]; lt += lpt[w*2+rr]; }
    int r = r0 + rr;
    g_z[((b*T_+r)*NH+n)*DH + k] = (r==0) ? 0.f : zs/lt;
  }
}

// ---------------- output projection ----------------
__global__ __launch_bounds__(256) void k_out(const float* __restrict__ WO,
                                             const float* __restrict__ bO,
                                             float* __restrict__ out){
  int tok0 = blockIdx.x*4;
  __shared__ float zs[4][512];
  int tid = threadIdx.x;
  for (int idx=tid; idx<4*512; idx+=256)
    zs[idx>>9][idx&511] = g_z[(tok0+(idx>>9))*512 + (idx&511)];
  __syncthreads();
  float acc[4][2];
  #pragma unroll
  for(int t=0;t<4;t++){acc[t][0]=0.f;acc[t][1]=0.f;}
  for (int nh=0; nh<512; nh++){
    float w0 = WO[nh*512 + tid      ];
    float w1 = WO[nh*512 + tid + 256];
    #pragma unroll
    for (int t=0;t<4;t++){
      float zv = zs[t][nh];
      acc[t][0] += zv*w0; acc[t][1] += zv*w1;
    }
  }
  float b0 = bO[tid], b1 = bO[tid+256];
  for (int t=0;t<4;t++){
    out[(tok0+t)*512 + tid      ] = acc[t][0] + b0;
    out[(tok0+t)*512 + tid + 256] = acc[t][1] + b1;
  }
}

// ---------------- launch ----------------
extern "C" void kernel_launch(void* const* d_in, const int* in_sizes, int n_in,
                              void* d_out, int out_size){
  const float* x  = (const float*)d_in[0];
  const float* wA = (const float*)d_in[1];
  const float* wB = (const float*)d_in[2];
  const float* wC = (const float*)d_in[3];
  const float* wD = (const float*)d_in[4];
  const float* wE = (const float*)d_in[5];
  const float* WK = (const float*)d_in[6];
  const float* WV = (const float*)d_in[7];
  const float* WO = (const float*)d_in[8];
  const float* bA = (const float*)d_in[9];
  const float* bB = (const float*)d_in[10];
  const float* bC = (const float*)d_in[11];
  const float* bD = (const float*)d_in[12];
  const float* bE = (const float*)d_in[13];
  const float* bO = (const float*)d_in[14];
  float* out = (float*)d_out;

  k_proj<<<dim3(48,40),256>>>(x,wA,wB,wC,wD,wE,bA,bB,bC,bD,bE);
  k_bsum<<<(B_*T_*DH+255)/256,256>>>();
  k_wkT<<<(NH*DH*4096+255)/256,256>>>(WK);
  size_t s1smem = (8192 + 16384)*sizeof(float);   // 96KB
  cudaFuncSetAttribute(k_step1, cudaFuncAttributeMaxDynamicSharedMemorySize, (int)s1smem);
  k_step1<<<dim3(24,16),256,s1smem>>>();
  size_t s2smem = (2048 + 192*65)*sizeof(float);
  cudaFuncSetAttribute(k_step2, cudaFuncAttributeMaxDynamicSharedMemorySize, (int)s2smem);
  k_step2<<<dim3(384,2),256,s2smem>>>();
  k_dv<<<dim3(48,2,16),256>>>(WV);
  size_t msmem = 56856*sizeof(float);             // ~222KB
  cudaFuncSetAttribute(k_main, cudaFuncAttributeMaxDynamicSharedMemorySize, (int)msmem);
  k_main<<<dim3(96,NH,B_),384,msmem>>>();
  k_out<<<96,256>>>(WO,bO,out);
}